// round 4
// baseline (speedup 1.0000x reference)
#include <cuda_runtime.h>
#include <cstdint>
#include <cstddef>

#define FEA    256
#define ATT    64
#define HLAST  10
#define TSTEP  12
#define NB     64
#define HDIM   2560
#define BTROWS 768       // NB * TSTEP
#define EROWS  196608    // BTROWS * FEA
#define HCN    (NB * HDIM)   // 163840

// ---- static device scratch (no runtime allocation allowed) ----
__device__ float g_enc[BTROWS * HDIM];          // [b*12+t][f*10+l]
__device__ float g_gx[TSTEP * 4 * NB * HDIM];   // [t][gate][b][j] : x-part preacts + bias
__device__ float g_pre[4 * NB * HDIM];          // [gate][b][j]    : full preacts, current step
__device__ float g_h[HCN];
__device__ float g_c[HCN];

__device__ __forceinline__ float to_tf32(float x) {
    uint32_t u;
    asm("cvt.rna.tf32.f32 %0, %1;" : "=r"(u) : "f"(x));
    return __uint_as_float(u);
}

__device__ __forceinline__ void mma_tf32(float* d, const uint32_t* a, const uint32_t* b) {
    asm volatile(
        "mma.sync.aligned.m16n8k8.row.col.f32.tf32.tf32.f32 "
        "{%0,%1,%2,%3}, {%4,%5,%6,%7}, {%8,%9}, {%0,%1,%2,%3};\n"
        : "+f"(d[0]), "+f"(d[1]), "+f"(d[2]), "+f"(d[3])
        : "r"(a[0]), "r"(a[1]), "r"(a[2]), "r"(a[3]), "r"(b[0]), "r"(b[1]));
}

// ---------------------------------------------------------------------------
__global__ void init_hc_kernel() {
    int idx = blockIdx.x * blockDim.x + threadIdx.x;
    if (idx < HCN) { g_h[idx] = 0.f; g_c[idx] = 0.f; }
}

// ---- encoder: g_enc = relu(relu(x@W0+b0)@W1+b1), warp per row-pair --------
__global__ void __launch_bounds__(256)
encoder_kernel(const float* __restrict__ x,
               const float* __restrict__ W0, const float* __restrict__ b0,
               const float* __restrict__ W1, const float* __restrict__ b1) {
    __shared__ float sW0[ATT * 128];
    __shared__ float sW1[128 * HLAST];
    __shared__ float sb0[128];
    __shared__ float sb1[HLAST];
    __shared__ float sx[8][2][ATT];

    for (int i = threadIdx.x; i < ATT * 128; i += blockDim.x) sW0[i] = W0[i];
    for (int i = threadIdx.x; i < 128 * HLAST; i += blockDim.x) sW1[i] = W1[i];
    if (threadIdx.x < 128) sb0[threadIdx.x] = b0[threadIdx.x];
    if (threadIdx.x < HLAST) sb1[threadIdx.x] = b1[threadIdx.x];
    __syncthreads();

    const int warp = threadIdx.x >> 5, lane = threadIdx.x & 31;
    const int gw = blockIdx.x * 8 + warp;
    const int stride = gridDim.x * 8;

    for (int pair = gw; pair < EROWS / 2; pair += stride) {
        const int row0 = pair * 2;
        const float* xr = x + (size_t)row0 * ATT;
        sx[warp][0][lane]      = xr[lane];
        sx[warp][0][lane + 32] = xr[lane + 32];
        sx[warp][1][lane]      = xr[ATT + lane];
        sx[warp][1][lane + 32] = xr[ATT + lane + 32];
        __syncwarp();

        float a0[4], a1[4];
        #pragma unroll
        for (int u = 0; u < 4; u++) { a0[u] = sb0[lane + 32 * u]; a1[u] = a0[u]; }
        #pragma unroll 8
        for (int k = 0; k < ATT; k++) {
            float x0 = sx[warp][0][k], x1 = sx[warp][1][k];
            #pragma unroll
            for (int u = 0; u < 4; u++) {
                float w = sW0[k * 128 + lane + 32 * u];
                a0[u] += x0 * w;
                a1[u] += x1 * w;
            }
        }
        #pragma unroll
        for (int u = 0; u < 4; u++) { a0[u] = fmaxf(a0[u], 0.f); a1[u] = fmaxf(a1[u], 0.f); }

        float p0[HLAST], p1[HLAST];
        #pragma unroll
        for (int l = 0; l < HLAST; l++) { p0[l] = 0.f; p1[l] = 0.f; }
        #pragma unroll
        for (int u = 0; u < 4; u++) {
            int j = lane + 32 * u;
            #pragma unroll
            for (int l = 0; l < HLAST; l++) {
                float w = sW1[j * HLAST + l];
                p0[l] += a0[u] * w;
                p1[l] += a1[u] * w;
            }
        }
        #pragma unroll
        for (int off = 16; off > 0; off >>= 1) {
            #pragma unroll
            for (int l = 0; l < HLAST; l++) {
                p0[l] += __shfl_down_sync(0xffffffffu, p0[l], off);
                p1[l] += __shfl_down_sync(0xffffffffu, p1[l], off);
            }
        }
        if (lane == 0) {
            int bt0 = row0 / FEA, f0 = row0 % FEA;
            int bt1 = (row0 + 1) / FEA, f1 = (row0 + 1) % FEA;
            #pragma unroll
            for (int l = 0; l < HLAST; l++) {
                g_enc[(size_t)bt0 * HDIM + f0 * HLAST + l] = fmaxf(p0[l] + sb1[l], 0.f);
                g_enc[(size_t)bt1 * HDIM + f1 * HLAST + l] = fmaxf(p1[l] + sb1[l], 0.f);
            }
        }
        __syncwarp();
    }
}

// ---- tf32 GEMM (BM=64, BN=64, BK=16, 4 warps, warp tile 32x32) ------------
// MODE 0: g_gx[t=by][g][b][:] = enc(b,t) @ W_g[0:2560,:] + bias_g   (M=768)
// MODE 1: g_pre[g][b][:] = g_gx[t][g][b][:] + g_h @ W_g[2560:5120,:] (M=64)
template<int MODE>
__global__ void __launch_bounds__(128)
gemm_tf32(const float* __restrict__ Wf_, const float* __restrict__ Wi_,
          const float* __restrict__ Wo_, const float* __restrict__ Wc_,
          const float* __restrict__ bf_, const float* __restrict__ bi_,
          const float* __restrict__ bo_, const float* __restrict__ bc_,
          int tstep) {
    __shared__ float sA[64][20];   // row stride 80B (16B aligned)
    __shared__ float sB[16][72];   // row stride 288B

    const int g = blockIdx.z;
    const float* W    = (g == 0) ? Wf_ : (g == 1) ? Wi_ : (g == 2) ? Wo_ : Wc_;
    const float* bias = (g == 0) ? bf_ : (g == 1) ? bi_ : (g == 2) ? bo_ : bc_;
    const int n0 = blockIdx.x * 64;
    const int by = blockIdx.y;
    const int tid = threadIdx.x, lane = tid & 31, warp = tid >> 5;
    const int wm = warp & 1, wn = warp >> 1;
    const int koff = (MODE == 0) ? 0 : HDIM;

    float acc[2][4][4];
    #pragma unroll
    for (int i = 0; i < 2; i++)
        #pragma unroll
        for (int j = 0; j < 4; j++)
            #pragma unroll
            for (int v = 0; v < 4; v++) acc[i][j][v] = 0.f;

    for (int k0 = 0; k0 < HDIM; k0 += 16) {
        #pragma unroll
        for (int i = 0; i < 2; i++) {          // A: 64x16
            int id = tid + i * 128;
            int r = id >> 2, c = (id & 3) * 4;
            const float* ap = (MODE == 0)
                ? g_enc + (size_t)(r * TSTEP + by) * HDIM + k0 + c
                : g_h   + (size_t)r * HDIM + k0 + c;
            float4 v = *(const float4*)ap;
            float4 w = make_float4(to_tf32(v.x), to_tf32(v.y), to_tf32(v.z), to_tf32(v.w));
            *(float4*)&sA[r][c] = w;
        }
        #pragma unroll
        for (int i = 0; i < 2; i++) {          // B: 16x64
            int id = tid + i * 128;
            int r = id >> 4, c = (id & 15) * 4;
            float4 v = *(const float4*)(W + (size_t)(koff + k0 + r) * HDIM + n0 + c);
            float4 w = make_float4(to_tf32(v.x), to_tf32(v.y), to_tf32(v.z), to_tf32(v.w));
            *(float4*)&sB[r][c] = w;
        }
        __syncthreads();

        #pragma unroll
        for (int kk = 0; kk < 16; kk += 8) {
            uint32_t afr[2][4], bfr[4][2];
            #pragma unroll
            for (int i = 0; i < 2; i++) {
                int rb = wm * 32 + i * 16;
                afr[i][0] = __float_as_uint(sA[rb +     (lane >> 2)][kk +     (lane & 3)]);
                afr[i][1] = __float_as_uint(sA[rb + 8 + (lane >> 2)][kk +     (lane & 3)]);
                afr[i][2] = __float_as_uint(sA[rb +     (lane >> 2)][kk + 4 + (lane & 3)]);
                afr[i][3] = __float_as_uint(sA[rb + 8 + (lane >> 2)][kk + 4 + (lane & 3)]);
            }
            #pragma unroll
            for (int j = 0; j < 4; j++) {
                int cb = wn * 32 + j * 8;
                bfr[j][0] = __float_as_uint(sB[kk +     (lane & 3)][cb + (lane >> 2)]);
                bfr[j][1] = __float_as_uint(sB[kk + 4 + (lane & 3)][cb + (lane >> 2)]);
            }
            #pragma unroll
            for (int i = 0; i < 2; i++)
                #pragma unroll
                for (int j = 0; j < 4; j++)
                    mma_tf32(acc[i][j], afr[i], bfr[j]);
        }
        __syncthreads();
    }

    #pragma unroll
    for (int i = 0; i < 2; i++) {
        int rb = wm * 32 + i * 16 + (lane >> 2);
        #pragma unroll
        for (int j = 0; j < 4; j++) {
            int cb = n0 + wn * 32 + j * 8 + (lane & 3) * 2;
            #pragma unroll
            for (int v = 0; v < 4; v++) {
                int row = rb + ((v >= 2) ? 8 : 0);
                int col = cb + (v & 1);
                float val = acc[i][j][v];
                if (MODE == 0) {
                    val += bias[col];
                    g_gx[((size_t)(by * 4 + g) * NB + row) * HDIM + col] = val;
                } else {
                    val += g_gx[((size_t)(tstep * 4 + g) * NB + row) * HDIM + col];
                    g_pre[((size_t)g * NB + row) * HDIM + col] = val;
                }
            }
        }
    }
}

// ---- LSTM elementwise update ----------------------------------------------
__global__ void lstm_update_kernel() {
    int idx = blockIdx.x * blockDim.x + threadIdx.x;
    if (idx >= HCN) return;
    float pf = g_pre[idx];
    float pi = g_pre[HCN + idx];
    float po = g_pre[2 * HCN + idx];
    float pc = g_pre[3 * HCN + idx];
    float f = 1.f / (1.f + expf(-pf));
    float i = 1.f / (1.f + expf(-pi));
    float o = 1.f / (1.f + expf(-po));
    float gg = tanhf(pc);
    float c = f * g_c[idx] + i * gg;
    g_c[idx] = c;
    g_h[idx] = o * tanhf(c);
}

// ---- final: out = relu(h.reshape(B,FEA,10)) @ Wfc + bfc --------------------
__global__ void __launch_bounds__(128)
final_fc_kernel(const float* __restrict__ Wfc, const float* __restrict__ bfc,
                float* __restrict__ out) {
    __shared__ float sW[HLAST * HLAST];
    __shared__ float sb[HLAST];
    if (threadIdx.x < HLAST * HLAST) sW[threadIdx.x] = Wfc[threadIdx.x];
    if (threadIdx.x < HLAST) sb[threadIdx.x] = bfc[threadIdx.x];
    __syncthreads();
    int idx = blockIdx.x * blockDim.x + threadIdx.x;   // (b, fea) pair
    if (idx >= NB * FEA) return;
    float hv[HLAST];
    #pragma unroll
    for (int j = 0; j < HLAST; j++) hv[j] = fmaxf(g_h[(size_t)idx * HLAST + j], 0.f);
    #pragma unroll
    for (int l = 0; l < HLAST; l++) {
        float s = sb[l];
        #pragma unroll
        for (int j = 0; j < HLAST; j++) s += hv[j] * sW[j * HLAST + l];
        out[(size_t)idx * HLAST + l] = s;
    }
}

// ---------------------------------------------------------------------------
extern "C" void kernel_launch(void* const* d_in, const int* in_sizes, int n_in,
                              void* d_out, int out_size) {
    const float* x   = (const float*)d_in[0];
    const float* W0  = (const float*)d_in[1];
    const float* b0  = (const float*)d_in[2];
    const float* W1  = (const float*)d_in[3];
    const float* b1  = (const float*)d_in[4];
    const float* Wf  = (const float*)d_in[5];
    const float* bf  = (const float*)d_in[6];
    const float* Wi  = (const float*)d_in[7];
    const float* bi  = (const float*)d_in[8];
    const float* Wo  = (const float*)d_in[9];
    const float* bo  = (const float*)d_in[10];
    const float* Wc  = (const float*)d_in[11];
    const float* bc  = (const float*)d_in[12];
    const float* Wfc = (const float*)d_in[13];
    const float* bfc = (const float*)d_in[14];
    float* out = (float*)d_out;

    init_hc_kernel<<<(HCN + 255) / 256, 256>>>();
    encoder_kernel<<<148, 256>>>(x, W0, b0, W1, b1);
    gemm_tf32<0><<<dim3(HDIM / 64, BTROWS / 64, 4), 128>>>(Wf, Wi, Wo, Wc, bf, bi, bo, bc, 0);
    for (int t = 0; t < TSTEP; t++) {
        gemm_tf32<1><<<dim3(HDIM / 64, 1, 4), 128>>>(Wf, Wi, Wo, Wc, bf, bi, bo, bc, t);
        lstm_update_kernel<<<(HCN + 255) / 256, 256>>>();
    }
    final_fc_kernel<<<(NB * FEA + 127) / 128, 128>>>(Wfc, bfc, out);
}

// round 7
// speedup vs baseline: 3.6743x; 3.6743x over previous
#include <cuda_runtime.h>
#include <cuda_fp16.h>
#include <cstdint>
#include <cstddef>

#define FEA    256
#define ATT    64
#define HLAST  10
#define TSTEP  12
#define NB     64
#define HDIM   2560          // lstm hidden size
#define KH     2560          // K per concat-half
#define BTROWS 768           // NB * TSTEP
#define EROWS  196608        // BTROWS * FEA
#define HCN    (NB * HDIM)   // 163840

// ---- static device scratch ----
__device__ __align__(256) __half g_w16[(size_t)4 * 2 * KH * KH];   // [gate][half][n][k] ~105MB
__device__ __align__(256) __half g_enc16[(size_t)BTROWS * HDIM];   // [b*12+t][n]
__device__ __align__(256) float  g_gx[(size_t)TSTEP * 4 * NB * HDIM]; // [t][g][b][n] x-part + bias
__device__ __align__(256) float  g_part[2][(size_t)4 * NB * HDIM]; // split-K partials [s][g][b][n]
__device__ __align__(256) float  g_h[HCN];
__device__ __align__(256) float  g_c[HCN];
__device__ __align__(256) __half g_h16[HCN];

__device__ __forceinline__ void cpasync16(void* sdst, const void* gsrc) {
    uint32_t s = (uint32_t)__cvta_generic_to_shared(sdst);
    asm volatile("cp.async.cg.shared.global [%0], [%1], 16;\n" :: "r"(s), "l"(gsrc));
}
__device__ __forceinline__ void cp_commit() { asm volatile("cp.async.commit_group;\n"); }
__device__ __forceinline__ void cp_wait1()  { asm volatile("cp.async.wait_group 1;\n"); }

__device__ __forceinline__ void mma_f16(float* d, const uint32_t* a, const uint32_t* b) {
    asm volatile(
        "mma.sync.aligned.m16n8k16.row.col.f32.f16.f16.f32 "
        "{%0,%1,%2,%3}, {%4,%5,%6,%7}, {%8,%9}, {%0,%1,%2,%3};\n"
        : "+f"(d[0]), "+f"(d[1]), "+f"(d[2]), "+f"(d[3])
        : "r"(a[0]), "r"(a[1]), "r"(a[2]), "r"(a[3]), "r"(b[0]), "r"(b[1]));
}

// ---- weight convert + transpose: W[k(5120)][n(2560)] f32 -> g_w16[g][half][n][k] f16
__global__ void __launch_bounds__(256)
convert_w_kernel(const float* __restrict__ Wf_, const float* __restrict__ Wi_,
                 const float* __restrict__ Wo_, const float* __restrict__ Wc_) {
    const int gz = blockIdx.z;
    const float* W = (gz == 0) ? Wf_ : (gz == 1) ? Wi_ : (gz == 2) ? Wo_ : Wc_;
    const int n0 = blockIdx.x * 32, k0 = blockIdx.y * 32;
    __shared__ __half t[32][33];
    for (int i = threadIdx.y; i < 32; i += 8)
        t[threadIdx.x][i] = __float2half(W[(size_t)(k0 + i) * KH + n0 + threadIdx.x]);
    __syncthreads();
    const int h = (k0 >= KH) ? 1 : 0;
    const int kk = k0 - h * KH;
    for (int i = threadIdx.y; i < 32; i += 8)
        g_w16[((size_t)(gz * 2 + h) * KH + n0 + i) * KH + kk + threadIdx.x] = t[i][threadIdx.x];
}

// ---------------------------------------------------------------------------
__global__ void init_hc_kernel() {
    int idx = blockIdx.x * blockDim.x + threadIdx.x;
    if (idx < HCN) { g_h[idx] = 0.f; g_c[idx] = 0.f; g_h16[idx] = __float2half(0.f); }
}

// ---- encoder: g_enc16 = relu(relu(x@W0+b0)@W1+b1) -------------------------
__global__ void __launch_bounds__(256)
encoder_kernel(const float* __restrict__ x,
               const float* __restrict__ W0, const float* __restrict__ b0,
               const float* __restrict__ W1, const float* __restrict__ b1) {
    __shared__ float sW0[ATT * 128];
    __shared__ float sW1[128 * HLAST];
    __shared__ float sb0[128];
    __shared__ float sb1[HLAST];
    __shared__ float sx[8][2][ATT];

    for (int i = threadIdx.x; i < ATT * 128; i += blockDim.x) sW0[i] = W0[i];
    for (int i = threadIdx.x; i < 128 * HLAST; i += blockDim.x) sW1[i] = W1[i];
    if (threadIdx.x < 128) sb0[threadIdx.x] = b0[threadIdx.x];
    if (threadIdx.x < HLAST) sb1[threadIdx.x] = b1[threadIdx.x];
    __syncthreads();

    const int warp = threadIdx.x >> 5, lane = threadIdx.x & 31;
    const int gw = blockIdx.x * 8 + warp;
    const int stride = gridDim.x * 8;

    for (int pair = gw; pair < EROWS / 2; pair += stride) {
        const int row0 = pair * 2;
        const float* xr = x + (size_t)row0 * ATT;
        sx[warp][0][lane]      = xr[lane];
        sx[warp][0][lane + 32] = xr[lane + 32];
        sx[warp][1][lane]      = xr[ATT + lane];
        sx[warp][1][lane + 32] = xr[ATT + lane + 32];
        __syncwarp();

        float a0[4], a1[4];
        #pragma unroll
        for (int u = 0; u < 4; u++) { a0[u] = sb0[lane + 32 * u]; a1[u] = a0[u]; }
        #pragma unroll 8
        for (int k = 0; k < ATT; k++) {
            float x0 = sx[warp][0][k], x1 = sx[warp][1][k];
            #pragma unroll
            for (int u = 0; u < 4; u++) {
                float w = sW0[k * 128 + lane + 32 * u];
                a0[u] += x0 * w;
                a1[u] += x1 * w;
            }
        }
        #pragma unroll
        for (int u = 0; u < 4; u++) { a0[u] = fmaxf(a0[u], 0.f); a1[u] = fmaxf(a1[u], 0.f); }

        float p0[HLAST], p1[HLAST];
        #pragma unroll
        for (int l = 0; l < HLAST; l++) { p0[l] = 0.f; p1[l] = 0.f; }
        #pragma unroll
        for (int u = 0; u < 4; u++) {
            int j = lane + 32 * u;
            #pragma unroll
            for (int l = 0; l < HLAST; l++) {
                float w = sW1[j * HLAST + l];
                p0[l] += a0[u] * w;
                p1[l] += a1[u] * w;
            }
        }
        #pragma unroll
        for (int off = 16; off > 0; off >>= 1) {
            #pragma unroll
            for (int l = 0; l < HLAST; l++) {
                p0[l] += __shfl_down_sync(0xffffffffu, p0[l], off);
                p1[l] += __shfl_down_sync(0xffffffffu, p1[l], off);
            }
        }
        if (lane == 0) {
            int bt0 = row0 / FEA, f0 = row0 % FEA;
            int bt1 = (row0 + 1) / FEA, f1 = (row0 + 1) % FEA;
            #pragma unroll
            for (int l = 0; l < HLAST; l++) {
                g_enc16[(size_t)bt0 * HDIM + f0 * HLAST + l] = __float2half(fmaxf(p0[l] + sb1[l], 0.f));
                g_enc16[(size_t)bt1 * HDIM + f1 * HLAST + l] = __float2half(fmaxf(p1[l] + sb1[l], 0.f));
            }
        }
        __syncwarp();
    }
}

// ---- fp16 tensor-core GEMM, BM=64 BN=64 BK=64, 8 warps, cp.async x2 buffer
// MODE 0: by = timestep t.  g_gx[t][g][b][n] = enc16(b,t) @ Wx + bias     (40 k-iters)
// MODE 1: by = k-split s.   g_part[s][g][b][n] = h16 @ Wh[s-half] (+gx if s==0)  (20 k-iters)
template<int MODE>
__global__ void __launch_bounds__(256)
gemm_fp16(const float* __restrict__ bf_, const float* __restrict__ bi_,
          const float* __restrict__ bo_, const float* __restrict__ bc_,
          int tstep) {
    __shared__ __align__(16) __half sA[2][64][72];
    __shared__ __align__(16) __half sB[2][64][72];

    const int gz = blockIdx.z;
    const int n0 = blockIdx.x * 64;
    const int by = blockIdx.y;
    const int tid = threadIdx.x, lane = tid & 31, warp = tid >> 5;
    const int wm = warp & 1, wn = warp >> 1;
    const int NIT   = (MODE == 0) ? 40 : 20;
    const int kbase = (MODE == 0) ? 0 : by * 1280;
    const __half* Bsrc = g_w16 + ((size_t)(gz * 2 + MODE) * KH + n0) * KH;

    float acc[2][2][4];
    #pragma unroll
    for (int i = 0; i < 2; i++)
        #pragma unroll
        for (int j = 0; j < 2; j++)
            #pragma unroll
            for (int v = 0; v < 4; v++) acc[i][j][v] = 0.f;

    auto load_stage = [&](int it, int buf) {
        const int k0 = kbase + it * 64;
        #pragma unroll
        for (int i = 0; i < 2; i++) {
            int id = tid + i * 256;
            int r = id >> 3, c = (id & 7) * 8;
            const __half* src = (MODE == 0)
                ? g_enc16 + (size_t)(r * TSTEP + by) * HDIM + k0 + c
                : g_h16   + (size_t)r * HDIM + k0 + c;
            cpasync16(&sA[buf][r][c], src);
        }
        #pragma unroll
        for (int i = 0; i < 2; i++) {
            int id = tid + i * 256;
            int r = id >> 3, c = (id & 7) * 8;
            cpasync16(&sB[buf][r][c], Bsrc + (size_t)r * KH + k0 + c);
        }
        cp_commit();
    };

    load_stage(0, 0);
    for (int it = 0; it < NIT; it++) {
        const int buf = it & 1;
        if (it + 1 < NIT) load_stage(it + 1, buf ^ 1);
        else cp_commit();
        cp_wait1();
        __syncthreads();

        #pragma unroll
        for (int kk = 0; kk < 64; kk += 16) {
            uint32_t af[2][4];
            #pragma unroll
            for (int mi = 0; mi < 2; mi++) {
                int m0 = wm * 32 + mi * 16;
                af[mi][0] = *(const uint32_t*)&sA[buf][m0 +     (lane >> 2)][kk +     (lane & 3) * 2];
                af[mi][1] = *(const uint32_t*)&sA[buf][m0 + 8 + (lane >> 2)][kk +     (lane & 3) * 2];
                af[mi][2] = *(const uint32_t*)&sA[buf][m0 +     (lane >> 2)][kk + 8 + (lane & 3) * 2];
                af[mi][3] = *(const uint32_t*)&sA[buf][m0 + 8 + (lane >> 2)][kk + 8 + (lane & 3) * 2];
            }
            uint32_t bfr[2][2];
            #pragma unroll
            for (int nj = 0; nj < 2; nj++) {
                int nn = wn * 16 + nj * 8;
                bfr[nj][0] = *(const uint32_t*)&sB[buf][nn + (lane >> 2)][kk +     (lane & 3) * 2];
                bfr[nj][1] = *(const uint32_t*)&sB[buf][nn + (lane >> 2)][kk + 8 + (lane & 3) * 2];
            }
            #pragma unroll
            for (int mi = 0; mi < 2; mi++)
                #pragma unroll
                for (int nj = 0; nj < 2; nj++)
                    mma_f16(acc[mi][nj], af[mi], bfr[nj]);
        }
        __syncthreads();
    }

    const float* bias = (gz == 0) ? bf_ : (gz == 1) ? bi_ : (gz == 2) ? bo_ : bc_;
    #pragma unroll
    for (int mi = 0; mi < 2; mi++) {
        int row = wm * 32 + mi * 16 + (lane >> 2);
        #pragma unroll
        for (int nj = 0; nj < 2; nj++) {
            int col = n0 + wn * 16 + nj * 8 + (lane & 3) * 2;
            float2 v0 = make_float2(acc[mi][nj][0], acc[mi][nj][1]);
            float2 v1 = make_float2(acc[mi][nj][2], acc[mi][nj][3]);
            if (MODE == 0) {
                float bx = bias[col], bY = bias[col + 1];
                v0.x += bx; v0.y += bY; v1.x += bx; v1.y += bY;
                *(float2*)&g_gx[((size_t)(by * 4 + gz) * NB + row) * HDIM + col]     = v0;
                *(float2*)&g_gx[((size_t)(by * 4 + gz) * NB + row + 8) * HDIM + col] = v1;
            } else {
                if (by == 0) {
                    float2 a0 = *(const float2*)&g_gx[((size_t)(tstep * 4 + gz) * NB + row) * HDIM + col];
                    float2 a1 = *(const float2*)&g_gx[((size_t)(tstep * 4 + gz) * NB + row + 8) * HDIM + col];
                    v0.x += a0.x; v0.y += a0.y; v1.x += a1.x; v1.y += a1.y;
                }
                *(float2*)&g_part[by][((size_t)gz * NB + row) * HDIM + col]     = v0;
                *(float2*)&g_part[by][((size_t)gz * NB + row + 8) * HDIM + col] = v1;
            }
        }
    }
}

// ---- LSTM elementwise update (sums split-K partials) ----------------------
__global__ void lstm_update_kernel() {
    int idx = blockIdx.x * blockDim.x + threadIdx.x;
    if (idx >= HCN) return;
    float pf = g_part[0][idx]           + g_part[1][idx];
    float pi = g_part[0][HCN + idx]     + g_part[1][HCN + idx];
    float po = g_part[0][2 * HCN + idx] + g_part[1][2 * HCN + idx];
    float pc = g_part[0][3 * HCN + idx] + g_part[1][3 * HCN + idx];
    float f = 1.f / (1.f + expf(-pf));
    float i = 1.f / (1.f + expf(-pi));
    float o = 1.f / (1.f + expf(-po));
    float gg = tanhf(pc);
    float c = f * g_c[idx] + i * gg;
    float h = o * tanhf(c);
    g_c[idx] = c;
    g_h[idx] = h;
    g_h16[idx] = __float2half(h);
}

// ---- final: out = relu(h.reshape(B,FEA,10)) @ Wfc + bfc --------------------
__global__ void __launch_bounds__(128)
final_fc_kernel(const float* __restrict__ Wfc, const float* __restrict__ bfc,
                float* __restrict__ out) {
    __shared__ float sW[HLAST * HLAST];
    __shared__ float sb[HLAST];
    if (threadIdx.x < HLAST * HLAST) sW[threadIdx.x] = Wfc[threadIdx.x];
    if (threadIdx.x < HLAST) sb[threadIdx.x] = bfc[threadIdx.x];
    __syncthreads();
    int idx = blockIdx.x * blockDim.x + threadIdx.x;   // (b, fea) pair
    if (idx >= NB * FEA) return;
    float hv[HLAST];
    #pragma unroll
    for (int j = 0; j < HLAST; j++) hv[j] = fmaxf(g_h[(size_t)idx * HLAST + j], 0.f);
    #pragma unroll
    for (int l = 0; l < HLAST; l++) {
        float s = sb[l];
        #pragma unroll
        for (int j = 0; j < HLAST; j++) s += hv[j] * sW[j * HLAST + l];
        out[(size_t)idx * HLAST + l] = s;
    }
}

// ---------------------------------------------------------------------------
extern "C" void kernel_launch(void* const* d_in, const int* in_sizes, int n_in,
                              void* d_out, int out_size) {
    const float* x   = (const float*)d_in[0];
    const float* W0  = (const float*)d_in[1];
    const float* b0  = (const float*)d_in[2];
    const float* W1  = (const float*)d_in[3];
    const float* b1  = (const float*)d_in[4];
    const float* Wf  = (const float*)d_in[5];
    const float* bf  = (const float*)d_in[6];
    const float* Wi  = (const float*)d_in[7];
    const float* bi  = (const float*)d_in[8];
    const float* Wo  = (const float*)d_in[9];
    const float* bo  = (const float*)d_in[10];
    const float* Wc  = (const float*)d_in[11];
    const float* bc  = (const float*)d_in[12];
    const float* Wfc = (const float*)d_in[13];
    const float* bfc = (const float*)d_in[14];
    float* out = (float*)d_out;

    convert_w_kernel<<<dim3(KH / 32, 2 * KH / 32, 4), dim3(32, 8)>>>(Wf, Wi, Wo, Wc);
    init_hc_kernel<<<(HCN + 255) / 256, 256>>>();
    encoder_kernel<<<296, 256>>>(x, W0, b0, W1, b1);
    gemm_fp16<0><<<dim3(HDIM / 64, TSTEP, 4), 256>>>(bf, bi, bo, bc, 0);
    for (int t = 0; t < TSTEP; t++) {
        gemm_fp16<1><<<dim3(HDIM / 64, 2, 4), 256>>>(bf, bi, bo, bc, t);
        lstm_update_kernel<<<(HCN + 255) / 256, 256>>>();
    }
    final_fc_kernel<<<(NB * FEA + 127) / 128, 128>>>(Wfc, bfc, out);
}